// round 14
// baseline (speedup 1.0000x reference)
#include <cuda_runtime.h>
#include <cuda_fp16.h>
#include <math.h>
#include <stdint.h>

// Problem constants
#define NN 32768        // B*K rows
#define DD 256          // feature dim
#define EE 8192         // codebook entries
#define ND (NN*DD)
#define CAP 128         // candidate list capacity per row
#define MARGIN 0.0025f  // fp16 rounding slack (2 * 2^-10 = 0.00196 + headroom)
#define FILT 0.00205f   // refine-time filter window (2 * 2^-10 + tiny headroom)
#define NTILES 16384    // 256 row-tiles x 64 code-tiles (128 codes each)
#define NG 296          // persistent grid (2 CTAs per SM on 148 SMs; all co-resident)

// ---------------- scratch (static __device__, no allocation) ----------------
__device__ __align__(16) __half g_Ah[NN * DD];
__device__ __align__(16) __half g_Bh[EE * DD];
__device__ __align__(16) float g_coden[EE * DD];   // fp32 normalized codebook
__device__ float g_invn[NN];                       // per-row 1/max(norm,eps)
__device__ float g_partial[NN / 8];
__device__ float g_scale;
__device__ float g_psim[NN / 8];                   // per-refine-group sim sums
__device__ int   g_counts[EE];
__device__ int   g_ccnt[NN];
__device__ unsigned int g_rowmax[NN];              // monotone shared row max (keyed)
__device__ unsigned long long g_cand[NN * CAP];    // packed (approx_v bits << 32) | col
__device__ unsigned int g_done;                    // finalize ticket (reset by releaser)
__device__ unsigned int g_bcnt[2];                 // grid barrier counters
__device__ unsigned int g_bflag[2];                // grid barrier sense flags

// ---------------- PTX helpers ----------------
__device__ __forceinline__ uint32_t smem_u32(const void* p) {
    uint32_t a;
    asm("{ .reg .u64 t; cvta.to.shared.u64 t, %1; cvt.u32.u64 %0, t; }" : "=r"(a) : "l"(p));
    return a;
}
#define CP_ASYNC16(dst, src) \
    asm volatile("cp.async.cg.shared.global [%0], [%1], 16;" :: "r"(dst), "l"(src) : "memory")
#define CP_COMMIT() asm volatile("cp.async.commit_group;" ::: "memory")
#define CP_WAIT1()  asm volatile("cp.async.wait_group 1;" ::: "memory")
#define CP_WAIT0()  asm volatile("cp.async.wait_group 0;" ::: "memory")
#define LDMATRIX_X4(r0, r1, r2, r3, addr) \
    asm volatile("ldmatrix.sync.aligned.m8n8.x4.shared.b16 {%0,%1,%2,%3}, [%4];" \
        : "=r"(r0), "=r"(r1), "=r"(r2), "=r"(r3) : "r"(addr))
#define MMA16816(c, a, b0, b1) \
    asm volatile("mma.sync.aligned.m16n8k16.row.col.f32.f16.f16.f32 " \
        "{%0,%1,%2,%3}, {%4,%5,%6,%7}, {%8,%9}, {%0,%1,%2,%3};" \
        : "+f"((c)[0]), "+f"((c)[1]), "+f"((c)[2]), "+f"((c)[3]) \
        : "r"((a)[0]), "r"((a)[1]), "r"((a)[2]), "r"((a)[3]), "r"(b0), "r"(b1))

// order-preserving float<->uint key (for atomicMax on possibly-negative floats)
__device__ __forceinline__ uint32_t fkey(float f) {
    uint32_t u = __float_as_uint(f);
    return (u & 0x80000000u) ? ~u : (u | 0x80000000u);
}
__device__ __forceinline__ float funkey(uint32_t k) {
    uint32_t u = (k & 0x80000000u) ? (k & 0x7fffffffu) : ~k;
    return __uint_as_float(u);
}

// ---- sense-reversing grid barrier (replay-safe: counter reset by releaser,
// flag alternates; all NG CTAs guaranteed co-resident) ----
__device__ __forceinline__ void grid_barrier(int b) {
    __syncthreads();
    if (threadIdx.x == 0) {
        unsigned old = *(volatile unsigned*)&g_bflag[b];
        __threadfence();
        unsigned pos = atomicAdd(&g_bcnt[b], 1u);
        if (pos == NG - 1u) {
            g_bcnt[b] = 0u;          // all arrivals done; safe to reset
            __threadfence();
            *(volatile unsigned*)&g_bflag[b] = old ^ 1u;
        } else {
            while (*(volatile unsigned*)&g_bflag[b] == old) __nanosleep(64);
        }
        __threadfence();
    }
    __syncthreads();
}

__device__ __forceinline__ float cand_dot(int cidx, const float4& f0, const float4& f1, int lane) {
    const float4* G = (const float4*)g_coden + (size_t)cidx * 64 + lane * 2;
    float4 g0 = G[0], g1 = G[1];
    return f0.x*g0.x + f0.y*g0.y + f0.z*g0.z + f0.w*g0.w
         + f1.x*g1.x + f1.y*g1.y + f1.z*g1.z + f1.w*g1.w;
}

#define SMEM_GEMM (65536 + 2 * 16384)

__device__ __forceinline__ uint32_t a_off(uint32_t r, uint32_t ch) {
    return r * 512u + (((ch & 0x18u) | ((ch ^ r) & 7u)) << 4);
}
__device__ __forceinline__ uint32_t b_off(uint32_t c, uint32_t ch) {
    return c * 128u + (((ch ^ c) & 7u) << 4);
}

// ======================= the mega-kernel =======================
__global__ void __launch_bounds__(256, 2) mega_kernel(
    float* __restrict__ out, const float* __restrict__ in, const float* __restrict__ cb
) {
    extern __shared__ __align__(1024) char smem[];
    const uint32_t sb = smem_u32(smem);
    const int tid = threadIdx.x;
    const int wid = tid >> 5;
    const int lane = tid & 31;
    __shared__ float sh8[8];

    // ================= P1: prep (strided virtual blocks) =================
    for (int vb = blockIdx.x; vb < 5120; vb += NG) {
        if (vb < 4096) {
            if (vb < 128) {
                int z = vb * 256 + tid;
                g_ccnt[z] = 0;
                g_rowmax[z] = 0u;
            }
            int row = vb * 8 + wid;
            const float4* r = (const float4*)in + (size_t)row * 64;
            float4 v0 = r[lane], v1 = r[lane + 32];
            float s = v0.x*v0.x + v0.y*v0.y + v0.z*v0.z + v0.w*v0.w
                    + v1.x*v1.x + v1.y*v1.y + v1.z*v1.z + v1.w*v1.w;
#pragma unroll
            for (int off = 16; off; off >>= 1) s += __shfl_down_sync(0xffffffffu, s, off);
            s = __shfl_sync(0xffffffffu, s, 0);
            float nrm = sqrtf(s);
            float inv = 1.0f / fmaxf(nrm, 1e-12f);
            float4 n0 = make_float4(v0.x*inv, v0.y*inv, v0.z*inv, v0.w*inv);
            float4 n1 = make_float4(v1.x*inv, v1.y*inv, v1.z*inv, v1.w*inv);
            __half2 h0a = __floats2half2_rn(n0.x, n0.y);
            __half2 h0b = __floats2half2_rn(n0.z, n0.w);
            __half2 h1a = __floats2half2_rn(n1.x, n1.y);
            __half2 h1b = __floats2half2_rn(n1.z, n1.w);
            uint2 h0 = make_uint2(*(uint32_t*)&h0a, *(uint32_t*)&h0b);
            uint2 h1 = make_uint2(*(uint32_t*)&h1a, *(uint32_t*)&h1b);
            ((uint2*)g_Ah)[(size_t)row * 64 + lane]      = h0;
            ((uint2*)g_Ah)[(size_t)row * 64 + 32 + lane] = h1;
            if (lane == 0) {
                g_invn[row] = inv;
                sh8[wid] = nrm;
            }
            __syncthreads();
            if (tid == 0) {
                float t = 0.f;
#pragma unroll
                for (int w = 0; w < 8; w++) t += sh8[w];
                g_partial[vb] = t;
            }
            __syncthreads();
        } else {
            int cbb = vb - 4096;
            if (cbb < 32) g_counts[cbb * 256 + tid] = 0;
            int row = cbb * 8 + wid;
            const float4* r = (const float4*)cb + (size_t)row * 64;
            float4 v0 = r[lane], v1 = r[lane + 32];
            float s = v0.x*v0.x + v0.y*v0.y + v0.z*v0.z + v0.w*v0.w
                    + v1.x*v1.x + v1.y*v1.y + v1.z*v1.z + v1.w*v1.w;
#pragma unroll
            for (int off = 16; off; off >>= 1) s += __shfl_down_sync(0xffffffffu, s, off);
            s = __shfl_sync(0xffffffffu, s, 0);
            float inv = 1.0f / fmaxf(sqrtf(s), 1e-12f);
            float4 n0 = make_float4(v0.x*inv, v0.y*inv, v0.z*inv, v0.w*inv);
            float4 n1 = make_float4(v1.x*inv, v1.y*inv, v1.z*inv, v1.w*inv);
            ((float4*)g_coden)[(size_t)row * 64 + lane]      = n0;
            ((float4*)g_coden)[(size_t)row * 64 + 32 + lane] = n1;
            __half2 h0a = __floats2half2_rn(n0.x, n0.y);
            __half2 h0b = __floats2half2_rn(n0.z, n0.w);
            __half2 h1a = __floats2half2_rn(n1.x, n1.y);
            __half2 h1b = __floats2half2_rn(n1.z, n1.w);
            uint2 h0 = make_uint2(*(uint32_t*)&h0a, *(uint32_t*)&h0b);
            uint2 h1 = make_uint2(*(uint32_t*)&h1a, *(uint32_t*)&h1b);
            ((uint2*)g_Bh)[(size_t)row * 64 + lane]      = h0;
            ((uint2*)g_Bh)[(size_t)row * 64 + 32 + lane] = h1;
        }
    }
    if (blockIdx.x == 0 && tid == 0) g_done = 0u;   // redundant with releaser reset; harmless

    grid_barrier(0);

    // ================= P2: mean-scale (block 0) + GEMM =================
    if (blockIdx.x == 0) {
        __shared__ float shp[256];
        float s = 0.f;
        for (int i = tid; i < NN / 8; i += 256) s += g_partial[i];
        shp[tid] = s; __syncthreads();
        for (int off = 128; off; off >>= 1) {
            if (tid < off) shp[tid] += shp[tid + off];
            __syncthreads();
        }
        if (tid == 0) g_scale = shp[0] / (float)NN;
        __syncthreads();
    }

    {
        const int warp_m = wid & 3;
        const int warp_n = wid >> 2;
        const uint4* Ag = (const uint4*)g_Ah;
        const uint4* Bg = (const uint4*)g_Bh;

        const int u0 = (int)(((long long)blockIdx.x * NTILES) / NG);
        const int u1 = (int)(((long long)(blockIdx.x + 1) * NTILES) / NG);

        int i = u0;
        while (i < u1) {
            const int rt = i >> 6;
            const int row0 = rt * 128;
            const int segend = min(u1, (rt + 1) << 6);
            const int nj = (segend - i) * 4;

            // ---- A tile load (own cp group) ----
#pragma unroll
            for (int l = 0; l < 16; l++) {
                int id = tid + l * 256;
                uint32_t r = id >> 5, ch = id & 31;
                CP_ASYNC16(sb + a_off(r, ch), Ag + (size_t)(row0 + r) * 32 + ch);
            }
            CP_COMMIT();

            float bestv[4], cached[4];
            int rows4[4];
#pragma unroll
            for (int s = 0; s < 4; s++) {
                rows4[s] = row0 + warp_m * 32 + (s >> 1) * 16 + (lane >> 2) + (s & 1) * 8;
                bestv[s] = -1e30f;
                cached[s] = funkey(__ldcg(&g_rowmax[rows4[s]]));
            }

#define ISSUE_STAGE(j) do { \
                int _tl = i + ((j) >> 2), _kc = (j) & 3; \
                int _cb = (_tl & 63) * 128; \
                uint32_t _bb = sb + 65536 + ((j) & 1) * 16384; \
                _Pragma("unroll") \
                for (int _l = 0; _l < 4; _l++) { \
                    int _id = tid + _l * 256; \
                    uint32_t _c = _id >> 3, _ch = _id & 7; \
                    CP_ASYNC16(_bb + b_off(_c, _ch), Bg + (size_t)(_cb + _c) * 32 + _kc * 8 + _ch); \
                } \
            } while (0)

            ISSUE_STAGE(0);
            CP_COMMIT();

            float c[2][8][4];

            for (int j = 0; j < nj; j++) {
                const int kc = j & 3;
                if (j + 1 < nj) {
                    ISSUE_STAGE(j + 1);
                    CP_COMMIT();
                    CP_WAIT1();
                } else {
                    CP_WAIT0();
                }
                __syncthreads();

                if (kc == 0) {
#pragma unroll
                    for (int mi = 0; mi < 2; mi++)
#pragma unroll
                        for (int ni = 0; ni < 8; ni++)
#pragma unroll
                            for (int r2 = 0; r2 < 4; r2++) c[mi][ni][r2] = 0.f;
                }

                const uint32_t bb = sb + 65536 + (j & 1) * 16384;
#pragma unroll
                for (int ks = 0; ks < 4; ks++) {
                    uint32_t a[2][4];
#pragma unroll
                    for (int mi = 0; mi < 2; mi++) {
                        uint32_t r = warp_m * 32 + mi * 16 + (lane & 15);
                        uint32_t ch = kc * 8 + ks * 2 + (lane >> 4);
                        uint32_t addr = sb + a_off(r, ch);
                        LDMATRIX_X4(a[mi][0], a[mi][1], a[mi][2], a[mi][3], addr);
                    }
                    uint32_t b[4][4];
#pragma unroll
                    for (int np = 0; np < 4; np++) {
                        uint32_t code = warp_n * 64 + np * 16 + (lane & 7) + ((lane & 16) ? 8 : 0);
                        uint32_t ch = ks * 2 + ((lane >> 3) & 1);
                        uint32_t addr = bb + b_off(code, ch);
                        LDMATRIX_X4(b[np][0], b[np][1], b[np][2], b[np][3], addr);
                    }
#pragma unroll
                    for (int mi = 0; mi < 2; mi++)
#pragma unroll
                        for (int ni = 0; ni < 8; ni++)
                            MMA16816(c[mi][ni], a[mi], b[ni >> 1][(ni & 1) * 2], b[ni >> 1][(ni & 1) * 2 + 1]);
                }

                if (kc == 3) {
                    const int colbase = ((i + (j >> 2)) & 63) * 128;
#pragma unroll
                    for (int s = 0; s < 4; s++) {
                        const int mi = s >> 1, hf = s & 1;
                        float m = c[mi][0][hf * 2];
#pragma unroll
                        for (int ni = 0; ni < 8; ni++) {
                            m = fmaxf(m, c[mi][ni][hf * 2]);
                            m = fmaxf(m, c[mi][ni][hf * 2 + 1]);
                        }
                        m = fmaxf(m, __shfl_xor_sync(0xffffffffu, m, 1));
                        m = fmaxf(m, __shfl_xor_sync(0xffffffffu, m, 2));
                        bestv[s] = fmaxf(fmaxf(bestv[s], m), cached[s]);
                        const float thr = bestv[s] - MARGIN;
                        const int row = rows4[s];
#pragma unroll
                        for (int ni = 0; ni < 8; ni++) {
#pragma unroll
                            for (int r2 = 0; r2 < 2; r2++) {
                                float v = c[mi][ni][hf * 2 + r2];
                                if (v >= thr) {
                                    int col = colbase + warp_n * 64 + ni * 8 + (lane & 3) * 2 + r2;
                                    int slot = atomicAdd(&g_ccnt[row], 1);
                                    if (slot < CAP) {
                                        unsigned long long pk =
                                            ((unsigned long long)__float_as_uint(v) << 32) | (unsigned)col;
                                        g_cand[row * CAP + slot] = pk;
                                    }
                                }
                            }
                        }
                        if ((lane & 3) == 0) atomicMax(&g_rowmax[row], fkey(bestv[s]));
                        cached[s] = funkey(__ldcg(&g_rowmax[row]));
                    }
                }
                __syncthreads();
            }
#undef ISSUE_STAGE
            i = segend;
        }
    }

    grid_barrier(1);

    // ================= P3: refine (strided virtual blocks) =================
    __shared__ float swarp[8];
    for (int rb = blockIdx.x; rb < NN / 8; rb += NG) {
        const int row = rb * 8 + wid;
        const float inv = g_invn[row];
        const float4* F = (const float4*)in + (size_t)row * 64 + lane * 2;
        float4 f0 = F[0], f1 = F[1];
        f0.x *= inv; f0.y *= inv; f0.z *= inv; f0.w *= inv;
        f1.x *= inv; f1.y *= inv; f1.z *= inv; f1.w *= inv;
        int cnt = g_ccnt[row];
        float bv = -1e30f;
        int bi = 0x7fffffff;

        if (cnt <= CAP) {
            const unsigned long long* cl = g_cand + (size_t)row * CAP;
            float vmax = -1e30f;
            for (int j = lane; j < cnt; j += 32)
                vmax = fmaxf(vmax, __uint_as_float((uint32_t)(cl[j] >> 32)));
#pragma unroll
            for (int off = 16; off; off >>= 1)
                vmax = fmaxf(vmax, __shfl_xor_sync(0xffffffffu, vmax, off));
            const float vthr = vmax - FILT;
            for (int j = 0; j < cnt; j++) {
                unsigned long long e = cl[j];
                float v = __uint_as_float((uint32_t)(e >> 32));
                if (v < vthr) continue;
                int cidx = (int)(uint32_t)(e & 0xffffffffu);
                float s = cand_dot(cidx, f0, f1, lane);
#pragma unroll
                for (int off = 16; off; off >>= 1) s += __shfl_xor_sync(0xffffffffu, s, off);
                if (s > bv || (s == bv && cidx < bi)) { bv = s; bi = cidx; }
            }
        } else {
            for (int cidx = 0; cidx < EE; cidx++) {
                float s = cand_dot(cidx, f0, f1, lane);
#pragma unroll
                for (int off = 16; off; off >>= 1) s += __shfl_xor_sync(0xffffffffu, s, off);
                if (s > bv || (s == bv && cidx < bi)) { bv = s; bi = cidx; }
            }
        }
        if (lane == 0) {
            swarp[wid] = bv;
            atomicAdd(&g_counts[bi], 1);
        }
        bi = __shfl_sync(0xffffffffu, bi, 0);

        float s = g_scale;
        const float4* Q = (const float4*)g_coden + (size_t)bi * 64 + lane * 2;
        float4 q0 = Q[0], q1 = Q[1];
        q0.x *= s; q0.y *= s; q0.z *= s; q0.w *= s;
        q1.x *= s; q1.y *= s; q1.z *= s; q1.w *= s;
        float4* O = (float4*)out + (size_t)row * 64 + lane * 2;
        O[0] = q0; O[1] = q1;

        __syncthreads();
        if (tid == 0) {
            float t = ((swarp[0] + swarp[1]) + (swarp[2] + swarp[3]))
                    + ((swarp[4] + swarp[5]) + (swarp[6] + swarp[7]));
            g_psim[rb] = t;
        }
        __syncthreads();
    }

    // ================= ticket finalize (last CTA) =================
    __threadfence();
    __syncthreads();
    __shared__ unsigned int s_last;
    if (tid == 0) s_last = (atomicAdd(&g_done, 1u) == NG - 1u) ? 1u : 0u;
    __syncthreads();
    if (!s_last) return;
    __threadfence();
    if (tid == 0) g_done = 0u;   // reset for next graph replay

    __shared__ float shf[256];
    float acc = 0.f;
    const float4* P4 = (const float4*)g_psim;
    for (int i = tid; i < NN / 8 / 4; i += 256) {
        float4 v = P4[i];
        acc += (v.x + v.y) + (v.z + v.w);
    }
    shf[tid] = acc; __syncthreads();
    for (int off = 128; off; off >>= 1) {
        if (tid < off) shf[tid] += shf[tid + off];
        __syncthreads();
    }
    float sumS = shf[0];
    __syncthreads();
    float h = 0.f;
    const int4* C4 = (const int4*)g_counts;
    for (int i = tid; i < EE / 4; i += 256) {
        int4 c = C4[i];
        float p0 = (float)c.x / (float)NN, p1 = (float)c.y / (float)NN;
        float p2 = (float)c.z / (float)NN, p3 = (float)c.w / (float)NN;
        h -= p0 * logf(p0 + 1e-10f) + p1 * logf(p1 + 1e-10f)
           + p2 * logf(p2 + 1e-10f) + p3 * logf(p3 + 1e-10f);
    }
    shf[tid] = h; __syncthreads();
    for (int off = 128; off; off >>= 1) {
        if (tid < off) shf[tid] += shf[tid + off];
        __syncthreads();
    }
    if (tid == 0) {
        float loss = 1.25f * (2.0f * (float)NN - 2.0f * sumS) / (float)ND;
        out[ND]     = loss;
        out[ND + 1] = expf(shf[0]);
    }
}

// ---------------- launch ----------------
extern "C" void kernel_launch(void* const* d_in, const int* in_sizes, int n_in,
                              void* d_out, int out_size) {
    const float* inputs   = (const float*)d_in[0];
    const float* codebook = (const float*)d_in[1];
    float* out = (float*)d_out;

    cudaFuncSetAttribute(mega_kernel, cudaFuncAttributeMaxDynamicSharedMemorySize, SMEM_GEMM);

    mega_kernel<<<NG, 256, SMEM_GEMM>>>(out, inputs, codebook);
}

// round 15
// speedup vs baseline: 1.0886x; 1.0886x over previous
#include <cuda_runtime.h>
#include <cuda_fp16.h>
#include <math.h>
#include <stdint.h>

// Problem constants
#define NN 32768        // B*K rows
#define DD 256          // feature dim
#define EE 8192         // codebook entries
#define ND (NN*DD)
#define CAP 128         // candidate list capacity per row
#define MARGIN 0.0025f  // fp16 rounding slack (2 * 2^-10 = 0.00196 + headroom)
#define FILT 0.00205f   // refine-time filter window (2 * 2^-10 + tiny headroom)
#define NTILES 16384    // 256 row-tiles x 64 code-tiles (128 codes each)
#define NG 296          // persistent grid (2 CTAs per SM on 148 SMs)

// ---------------- scratch (static __device__, no allocation) ----------------
__device__ __align__(16) __half g_Ah[NN * DD];
__device__ __align__(16) __half g_Bh[EE * DD];
__device__ float g_cinv[EE];                       // per-code 1/max(norm,eps)
__device__ float g_invn[NN];                       // per-row 1/max(norm,eps)
__device__ float g_partial[NN / 8];
__device__ float g_scale;
__device__ float g_psim[NN / 8];                   // per-refine-block sim sums
__device__ int   g_counts[EE];
__device__ int   g_ccnt[NN];
__device__ unsigned int g_rowmax[NN];              // monotone shared row max (keyed)
__device__ unsigned long long g_cand[NN * CAP];    // packed (approx_v bits << 32) | col

// ---------------- PTX helpers ----------------
__device__ __forceinline__ uint32_t smem_u32(const void* p) {
    uint32_t a;
    asm("{ .reg .u64 t; cvta.to.shared.u64 t, %1; cvt.u32.u64 %0, t; }" : "=r"(a) : "l"(p));
    return a;
}
#define CP_ASYNC16(dst, src) \
    asm volatile("cp.async.cg.shared.global [%0], [%1], 16;" :: "r"(dst), "l"(src) : "memory")
#define CP_COMMIT() asm volatile("cp.async.commit_group;" ::: "memory")
#define CP_WAIT1()  asm volatile("cp.async.wait_group 1;" ::: "memory")
#define CP_WAIT0()  asm volatile("cp.async.wait_group 0;" ::: "memory")
#define LDMATRIX_X4(r0, r1, r2, r3, addr) \
    asm volatile("ldmatrix.sync.aligned.m8n8.x4.shared.b16 {%0,%1,%2,%3}, [%4];" \
        : "=r"(r0), "=r"(r1), "=r"(r2), "=r"(r3) : "r"(addr))
#define MMA16816(c, a, b0, b1) \
    asm volatile("mma.sync.aligned.m16n8k16.row.col.f32.f16.f16.f32 " \
        "{%0,%1,%2,%3}, {%4,%5,%6,%7}, {%8,%9}, {%0,%1,%2,%3};" \
        : "+f"((c)[0]), "+f"((c)[1]), "+f"((c)[2]), "+f"((c)[3]) \
        : "r"((a)[0]), "r"((a)[1]), "r"((a)[2]), "r"((a)[3]), "r"(b0), "r"(b1))

// order-preserving float<->uint key (for atomicMax on possibly-negative floats)
__device__ __forceinline__ uint32_t fkey(float f) {
    uint32_t u = __float_as_uint(f);
    return (u & 0x80000000u) ? ~u : (u | 0x80000000u);
}
__device__ __forceinline__ float funkey(uint32_t k) {
    uint32_t u = (k & 0x80000000u) ? (k & 0x7fffffffu) : ~k;
    return __uint_as_float(u);
}

// ---------------- fused prep: normalize inputs + codebook -------------------
__global__ void prep_kernel(const float* __restrict__ in, const float* __restrict__ cb) {
    const int warp = threadIdx.x >> 5, lane = threadIdx.x & 31;

    if (blockIdx.x < 4096) {
        if (blockIdx.x < 128) {
            int z = blockIdx.x * 256 + threadIdx.x;
            g_ccnt[z] = 0;
            g_rowmax[z] = 0u;        // key(-inf)
        }
        __shared__ float sh[8];
        int row = blockIdx.x * 8 + warp;
        const float4* r = (const float4*)in + (size_t)row * 64;
        float4 v0 = r[lane], v1 = r[lane + 32];
        float s = v0.x*v0.x + v0.y*v0.y + v0.z*v0.z + v0.w*v0.w
                + v1.x*v1.x + v1.y*v1.y + v1.z*v1.z + v1.w*v1.w;
#pragma unroll
        for (int off = 16; off; off >>= 1) s += __shfl_down_sync(0xffffffffu, s, off);
        s = __shfl_sync(0xffffffffu, s, 0);
        float nrm = sqrtf(s);
        float inv = 1.0f / fmaxf(nrm, 1e-12f);
        float4 n0 = make_float4(v0.x*inv, v0.y*inv, v0.z*inv, v0.w*inv);
        float4 n1 = make_float4(v1.x*inv, v1.y*inv, v1.z*inv, v1.w*inv);
        __half2 h0a = __floats2half2_rn(n0.x, n0.y);
        __half2 h0b = __floats2half2_rn(n0.z, n0.w);
        __half2 h1a = __floats2half2_rn(n1.x, n1.y);
        __half2 h1b = __floats2half2_rn(n1.z, n1.w);
        uint2 h0 = make_uint2(*(uint32_t*)&h0a, *(uint32_t*)&h0b);
        uint2 h1 = make_uint2(*(uint32_t*)&h1a, *(uint32_t*)&h1b);
        ((uint2*)g_Ah)[(size_t)row * 64 + lane]      = h0;
        ((uint2*)g_Ah)[(size_t)row * 64 + 32 + lane] = h1;
        if (lane == 0) {
            g_invn[row] = inv;
            sh[warp] = nrm;
        }
        __syncthreads();
        if (threadIdx.x == 0) {
            float t = 0.f;
#pragma unroll
            for (int w = 0; w < 8; w++) t += sh[w];
            g_partial[blockIdx.x] = t;
        }
    } else {
        int cbb = blockIdx.x - 4096;
        if (cbb < 32) g_counts[cbb * 256 + threadIdx.x] = 0;
        int row = cbb * 8 + warp;
        const float4* r = (const float4*)cb + (size_t)row * 64;
        float4 v0 = r[lane], v1 = r[lane + 32];
        float s = v0.x*v0.x + v0.y*v0.y + v0.z*v0.z + v0.w*v0.w
                + v1.x*v1.x + v1.y*v1.y + v1.z*v1.z + v1.w*v1.w;
#pragma unroll
        for (int off = 16; off; off >>= 1) s += __shfl_down_sync(0xffffffffu, s, off);
        s = __shfl_sync(0xffffffffu, s, 0);
        float inv = 1.0f / fmaxf(sqrtf(s), 1e-12f);
        float4 n0 = make_float4(v0.x*inv, v0.y*inv, v0.z*inv, v0.w*inv);
        float4 n1 = make_float4(v1.x*inv, v1.y*inv, v1.z*inv, v1.w*inv);
        __half2 h0a = __floats2half2_rn(n0.x, n0.y);
        __half2 h0b = __floats2half2_rn(n0.z, n0.w);
        __half2 h1a = __floats2half2_rn(n1.x, n1.y);
        __half2 h1b = __floats2half2_rn(n1.z, n1.w);
        uint2 h0 = make_uint2(*(uint32_t*)&h0a, *(uint32_t*)&h0b);
        uint2 h1 = make_uint2(*(uint32_t*)&h1a, *(uint32_t*)&h1b);
        ((uint2*)g_Bh)[(size_t)row * 64 + lane]      = h0;
        ((uint2*)g_Bh)[(size_t)row * 64 + 32 + lane] = h1;
        if (lane == 0) g_cinv[row] = inv;
    }
}

// ---------------- balanced persistent fp16 GEMM + candidate capture ---------
// R8/R13 configuration (measured best): 2-stage double-buffered cp.async, f32
// accumulators, contiguous tile ranges per CTA, shared monotone row max.
#define SMEM_GEMM (65536 + 2 * 16384)

__device__ __forceinline__ uint32_t a_off(uint32_t r, uint32_t ch) {
    return r * 512u + (((ch & 0x18u) | ((ch ^ r) & 7u)) << 4);
}
__device__ __forceinline__ uint32_t b_off(uint32_t c, uint32_t ch) {
    return c * 128u + (((ch ^ c) & 7u) << 4);
}

__global__ void __launch_bounds__(256, 2) hh_gemm_kernel() {
    extern __shared__ __align__(1024) char smem[];
    const uint32_t sb = smem_u32(smem);
    const int tid = threadIdx.x;
    const int wid = tid >> 5;
    const int lane = tid & 31;
    const int warp_m = wid & 3;
    const int warp_n = wid >> 2;
    const uint4* Ag = (const uint4*)g_Ah;
    const uint4* Bg = (const uint4*)g_Bh;

    // fused deterministic mean-scale reduction (g_partial complete: prep done)
    if (blockIdx.x == 0) {
        __shared__ float shp[256];
        float s = 0.f;
        for (int i = tid; i < NN / 8; i += 256) s += g_partial[i];
        shp[tid] = s; __syncthreads();
        for (int off = 128; off; off >>= 1) {
            if (tid < off) shp[tid] += shp[tid + off];
            __syncthreads();
        }
        if (tid == 0) g_scale = shp[0] / (float)NN;
    }

    const int u0 = (int)(((long long)blockIdx.x * NTILES) / NG);
    const int u1 = (int)(((long long)(blockIdx.x + 1) * NTILES) / NG);

    int i = u0;
    while (i < u1) {
        const int rt = i >> 6;
        const int row0 = rt * 128;
        const int segend = min(u1, (rt + 1) << 6);
        const int nj = (segend - i) * 4;

        // ---- A tile load (own cp group) ----
#pragma unroll
        for (int l = 0; l < 16; l++) {
            int id = tid + l * 256;          // 0..4095
            uint32_t r = id >> 5, ch = id & 31;
            CP_ASYNC16(sb + a_off(r, ch), Ag + (size_t)(row0 + r) * 32 + ch);
        }
        CP_COMMIT();

        // ---- per-segment row state ----
        float bestv[4], cached[4];
        int rows4[4];
#pragma unroll
        for (int s = 0; s < 4; s++) {
            rows4[s] = row0 + warp_m * 32 + (s >> 1) * 16 + (lane >> 2) + (s & 1) * 8;
            bestv[s] = -1e30f;
            cached[s] = funkey(__ldcg(&g_rowmax[rows4[s]]));
        }

        // issue stage j: tile = i + (j>>2), k-chunk kc = j&3, buffer j&1
#define ISSUE_STAGE(j) do { \
            int _tl = i + ((j) >> 2), _kc = (j) & 3; \
            int _cb = (_tl & 63) * 128; \
            uint32_t _bb = sb + 65536 + ((j) & 1) * 16384; \
            _Pragma("unroll") \
            for (int _l = 0; _l < 4; _l++) { \
                int _id = tid + _l * 256; \
                uint32_t _c = _id >> 3, _ch = _id & 7; \
                CP_ASYNC16(_bb + b_off(_c, _ch), Bg + (size_t)(_cb + _c) * 32 + _kc * 8 + _ch); \
            } \
        } while (0)

        ISSUE_STAGE(0);
        CP_COMMIT();

        float c[2][8][4];

        for (int j = 0; j < nj; j++) {
            const int kc = j & 3;
            if (j + 1 < nj) {
                ISSUE_STAGE(j + 1);
                CP_COMMIT();
                CP_WAIT1();
            } else {
                CP_WAIT0();
            }
            __syncthreads();

            if (kc == 0) {
#pragma unroll
                for (int mi = 0; mi < 2; mi++)
#pragma unroll
                    for (int ni = 0; ni < 8; ni++)
#pragma unroll
                        for (int r2 = 0; r2 < 4; r2++) c[mi][ni][r2] = 0.f;
            }

            const uint32_t bb = sb + 65536 + (j & 1) * 16384;
#pragma unroll
            for (int ks = 0; ks < 4; ks++) {
                uint32_t a[2][4];
#pragma unroll
                for (int mi = 0; mi < 2; mi++) {
                    uint32_t r = warp_m * 32 + mi * 16 + (lane & 15);
                    uint32_t ch = kc * 8 + ks * 2 + (lane >> 4);
                    uint32_t addr = sb + a_off(r, ch);
                    LDMATRIX_X4(a[mi][0], a[mi][1], a[mi][2], a[mi][3], addr);
                }
                uint32_t b[4][4];
#pragma unroll
                for (int np = 0; np < 4; np++) {
                    uint32_t code = warp_n * 64 + np * 16 + (lane & 7) + ((lane & 16) ? 8 : 0);
                    uint32_t ch = ks * 2 + ((lane >> 3) & 1);
                    uint32_t addr = bb + b_off(code, ch);
                    LDMATRIX_X4(b[np][0], b[np][1], b[np][2], b[np][3], addr);
                }
#pragma unroll
                for (int mi = 0; mi < 2; mi++)
#pragma unroll
                    for (int ni = 0; ni < 8; ni++)
                        MMA16816(c[mi][ni], a[mi], b[ni >> 1][(ni & 1) * 2], b[ni >> 1][(ni & 1) * 2 + 1]);
            }

            // ---- per-tile epilogue ----
            if (kc == 3) {
                const int colbase = ((i + (j >> 2)) & 63) * 128;
#pragma unroll
                for (int s = 0; s < 4; s++) {
                    const int mi = s >> 1, hf = s & 1;
                    float m = c[mi][0][hf * 2];
#pragma unroll
                    for (int ni = 0; ni < 8; ni++) {
                        m = fmaxf(m, c[mi][ni][hf * 2]);
                        m = fmaxf(m, c[mi][ni][hf * 2 + 1]);
                    }
                    m = fmaxf(m, __shfl_xor_sync(0xffffffffu, m, 1));
                    m = fmaxf(m, __shfl_xor_sync(0xffffffffu, m, 2));
                    const bool improved = (m > fmaxf(bestv[s], cached[s]));
                    bestv[s] = fmaxf(fmaxf(bestv[s], m), cached[s]);
                    const float thr = bestv[s] - MARGIN;
                    const int row = rows4[s];
#pragma unroll
                    for (int ni = 0; ni < 8; ni++) {
#pragma unroll
                        for (int r2 = 0; r2 < 2; r2++) {
                            float v = c[mi][ni][hf * 2 + r2];
                            if (v >= thr) {
                                int col = colbase + warp_n * 64 + ni * 8 + (lane & 3) * 2 + r2;
                                int slot = atomicAdd(&g_ccnt[row], 1);
                                if (slot < CAP) {
                                    unsigned long long pk =
                                        ((unsigned long long)__float_as_uint(v) << 32) | (unsigned)col;
                                    g_cand[row * CAP + slot] = pk;
                                }
                            }
                        }
                    }
                    // publish only when this tile raised the row max; refresh always
                    if (improved && (lane & 3) == 0) atomicMax(&g_rowmax[row], fkey(bestv[s]));
                    cached[s] = funkey(__ldcg(&g_rowmax[row]));
                }
            }
            __syncthreads();
        }
#undef ISSUE_STAGE
        i = segend;
    }
}

// ---------------- exact fp32 refine + bincount + output + psim partials -----
__device__ __forceinline__ float cand_dot(const float* __restrict__ cb, int cidx,
                                          const float4& f0, const float4& f1, int lane) {
    const float4* G = (const float4*)cb + (size_t)cidx * 64 + lane * 2;
    float4 g0 = G[0], g1 = G[1];
    return f0.x*g0.x + f0.y*g0.y + f0.z*g0.z + f0.w*g0.w
         + f1.x*g1.x + f1.y*g1.y + f1.z*g1.z + f1.w*g1.w;
}

__global__ void refine_kernel(float* __restrict__ out, const float* __restrict__ in,
                              const float* __restrict__ cb) {
    const int wid = threadIdx.x >> 5, lane = threadIdx.x & 31;
    const int row = blockIdx.x * 8 + wid;
    const float inv = g_invn[row];
    const float4* F = (const float4*)in + (size_t)row * 64 + lane * 2;
    float4 f0 = F[0], f1 = F[1];
    f0.x *= inv; f0.y *= inv; f0.z *= inv; f0.w *= inv;
    f1.x *= inv; f1.y *= inv; f1.z *= inv; f1.w *= inv;
    int cnt = g_ccnt[row];
    float bv = -1e30f;
    int bi = 0x7fffffff;

    if (cnt <= CAP) {
        const unsigned long long* cl = g_cand + (size_t)row * CAP;
        // pass 1: max approx value over candidates (includes global approx argmax)
        float vmax = -1e30f;
        for (int j = lane; j < cnt; j += 32)
            vmax = fmaxf(vmax, __uint_as_float((uint32_t)(cl[j] >> 32)));
#pragma unroll
        for (int off = 16; off; off >>= 1)
            vmax = fmaxf(vmax, __shfl_xor_sync(0xffffffffu, vmax, off));
        const float vthr = vmax - FILT;
        // pass 2: exact dot only for survivors (1-3 typical)
        for (int j = 0; j < cnt; j++) {
            unsigned long long e = cl[j];
            float v = __uint_as_float((uint32_t)(e >> 32));
            if (v < vthr) continue;
            int cidx = (int)(uint32_t)(e & 0xffffffffu);
            float s = cand_dot(cb, cidx, f0, f1, lane);
#pragma unroll
            for (int off = 16; off; off >>= 1) s += __shfl_xor_sync(0xffffffffu, s, off);
            s *= g_cinv[cidx];
            if (s > bv || (s == bv && cidx < bi)) { bv = s; bi = cidx; }
        }
    } else {
        // overflow fallback: exact scan over all codes
        for (int cidx = 0; cidx < EE; cidx++) {
            float s = cand_dot(cb, cidx, f0, f1, lane);
#pragma unroll
            for (int off = 16; off; off >>= 1) s += __shfl_xor_sync(0xffffffffu, s, off);
            s *= g_cinv[cidx];
            if (s > bv || (s == bv && cidx < bi)) { bv = s; bi = cidx; }
        }
    }
    __shared__ float swarp[8];
    if (lane == 0) {
        swarp[wid] = bv;
        atomicAdd(&g_counts[bi], 1);   // fused bincount (integer: deterministic)
    }
    bi = __shfl_sync(0xffffffffu, bi, 0);

    // fused quantized output: out[row] = (cb[bi] * cinv[bi]) * g_scale
    // (elementwise normalize-then-scale, matching the reference rounding order)
    float ci = g_cinv[bi];
    float s = g_scale;
    const float4* Q = (const float4*)cb + (size_t)bi * 64 + lane * 2;
    float4 q0 = Q[0], q1 = Q[1];
    q0.x = (q0.x * ci) * s; q0.y = (q0.y * ci) * s;
    q0.z = (q0.z * ci) * s; q0.w = (q0.w * ci) * s;
    q1.x = (q1.x * ci) * s; q1.y = (q1.y * ci) * s;
    q1.z = (q1.z * ci) * s; q1.w = (q1.w * ci) * s;
    float4* O = (float4*)out + (size_t)row * 64 + lane * 2;
    O[0] = q0; O[1] = q1;

    // per-block sim partial (fixed order: 8 warps in index order)
    __syncthreads();
    if (threadIdx.x == 0) {
        float t = ((swarp[0] + swarp[1]) + (swarp[2] + swarp[3]))
                + ((swarp[4] + swarp[5]) + (swarp[6] + swarp[7]));
        g_psim[blockIdx.x] = t;
    }
}

// ---------------- loss + perplexity (small: 4K partials + 8K counts) --------
__global__ void finalize_kernel(float* __restrict__ out) {
    __shared__ float sh[1024];
    int tid = threadIdx.x;
    float s = 0.f;
    const float4* P4 = (const float4*)g_psim;
    for (int i = tid; i < NN / 8 / 4; i += 1024) {
        float4 v = P4[i];
        s += (v.x + v.y) + (v.z + v.w);
    }
    sh[tid] = s; __syncthreads();
    for (int off = 512; off; off >>= 1) {
        if (tid < off) sh[tid] += sh[tid + off];
        __syncthreads();
    }
    float sumS = sh[0];
    __syncthreads();
    float h = 0.f;
    const int4* C4 = (const int4*)g_counts;
    for (int i = tid; i < EE / 4; i += 1024) {
        int4 c = C4[i];
        float p0 = (float)c.x / (float)NN, p1 = (float)c.y / (float)NN;
        float p2 = (float)c.z / (float)NN, p3 = (float)c.w / (float)NN;
        h -= p0 * logf(p0 + 1e-10f) + p1 * logf(p1 + 1e-10f)
           + p2 * logf(p2 + 1e-10f) + p3 * logf(p3 + 1e-10f);
    }
    sh[tid] = h; __syncthreads();
    for (int off = 512; off; off >>= 1) {
        if (tid < off) sh[tid] += sh[tid + off];
        __syncthreads();
    }
    if (tid == 0) {
        float loss = 1.25f * (2.0f * (float)NN - 2.0f * sumS) / (float)ND;
        out[ND]     = loss;
        out[ND + 1] = expf(sh[0]);
    }
}

// ---------------- launch ----------------
extern "C" void kernel_launch(void* const* d_in, const int* in_sizes, int n_in,
                              void* d_out, int out_size) {
    const float* inputs   = (const float*)d_in[0];
    const float* codebook = (const float*)d_in[1];
    float* out = (float*)d_out;

    cudaFuncSetAttribute(hh_gemm_kernel, cudaFuncAttributeMaxDynamicSharedMemorySize, SMEM_GEMM);

    prep_kernel<<<5120, 256>>>(inputs, codebook);
    hh_gemm_kernel<<<NG, 256, SMEM_GEMM>>>();
    refine_kernel<<<NN / 8, 256>>>(out, inputs, codebook);
    finalize_kernel<<<1, 1024>>>(out);
}